// round 6
// baseline (speedup 1.0000x reference)
#include <cuda_runtime.h>
#include <cuda_bf16.h>
#include <math.h>
#include <stdint.h>

// ---------------------------------------------------------------------------
// Model dims
// ---------------------------------------------------------------------------
#define DIM   1024
#define FFDIM 4096
#define VOC   32000
#define SEQ   1024
#define BATCH 2
#define MTOK  (BATCH * SEQ)

#define LAYER0_OFF   32768000LL
#define LAYER_STRIDE 16777216LL
#define NWEIGHT      (2 * LAYER_STRIDE + (long long)VOC * DIM)

// ---------------------------------------------------------------------------
// Scratch
// ---------------------------------------------------------------------------
__device__ float g_w  [NWEIGHT];          // tf32-rounded weights
__device__ float g_h  [MTOK * DIM];
__device__ float g_qkv[MTOK * 3 * DIM];   // q,k interleaved-pair layout; v plain
__device__ float g_vt [BATCH * DIM * SEQ];
__device__ float g_s  [BATCH * SEQ * SEQ];
__device__ float g_a  [MTOK * DIM];
__device__ float g_t  [MTOK * FFDIM];

// ---------------------------------------------------------------------------
// helpers
// ---------------------------------------------------------------------------
__device__ __forceinline__ uint32_t f2tf32(float x) {
    uint32_t r;
    asm("cvt.rna.tf32.f32 %0, %1;" : "=r"(r) : "f"(x));
    return r;
}
__device__ __forceinline__ float round_tf32(float x) {
    return __uint_as_float(f2tf32(x));
}
__device__ __forceinline__ uint32_t smem_u32(const void* p) {
    uint32_t a;
    asm("{ .reg .u64 t; cvta.to.shared.u64 t, %1; cvt.u32.u64 %0, t; }" : "=r"(a) : "l"(p));
    return a;
}
#define CP_ASYNC16(dst, src) \
    asm volatile("cp.async.cg.shared.global [%0], [%1], 16;" :: "r"(dst), "l"(src))
#define CP_COMMIT() asm volatile("cp.async.commit_group;" ::: "memory")
#define CP_WAIT(n)  asm volatile("cp.async.wait_group %0;" :: "n"(n) : "memory")

__device__ __forceinline__ void mma16n8k8(float c[4], const uint32_t a[4],
                                          const uint32_t b[2]) {
    asm volatile(
        "mma.sync.aligned.m16n8k8.row.col.f32.tf32.tf32.f32 "
        "{%0,%1,%2,%3}, {%4,%5,%6,%7}, {%8,%9}, {%0,%1,%2,%3};"
        : "+f"(c[0]), "+f"(c[1]), "+f"(c[2]), "+f"(c[3])
        : "r"(a[0]), "r"(a[1]), "r"(a[2]), "r"(a[3]), "r"(b[0]), "r"(b[1]));
}

// ---------------------------------------------------------------------------
// tf32 GEMM, cp.async 4-stage.  C[M,N] = alpha*A@B^T (+R), modes:
//   PLAIN: write as-is        ROUND: tf32-round outputs
//   SILU : B rows interleaved gate/up; epilogue writes silu(g)*u to N/2 cols
//   ROPE : B rows = qkv with q,k pair-interleave; epilogue applies RoPE
// ---------------------------------------------------------------------------
#define MODE_PLAIN 0
#define MODE_ROUND 1
#define MODE_SILU  2
#define MODE_ROPE  3

#define BM 128
#define BN 128
#define BK 16
#define RS 20
#define STG_F   (2 * 128 * RS)
#define B_F     (128 * RS)
#define STAGES  4
#define GEMM_SMEM (STAGES * STG_F * 4)

template<int MODE>
__global__ __launch_bounds__(256, 2)
void tf32_gemm(const float* __restrict__ A, int lda, long long sAz,
               const float* __restrict__ B, int ldb, long long sBz,
               float* __restrict__ C, int ldc, long long sCz,
               const float* __restrict__ R, int K, float alpha)
{
    extern __shared__ float sm[];
    const uint32_t smb = smem_u32(sm);

    const int tid  = threadIdx.x;
    const int warp = tid >> 5, lane = tid & 31;
    const int wm = warp & 1;
    const int wn = warp >> 1;
    const int g  = lane >> 2;
    const int tg = lane & 3;

    const long long bz = blockIdx.z;
    A += bz * sAz;  B += bz * sBz;  C += bz * sCz;
    const float* Rp = R ? (R + bz * sCz) : nullptr;
    const int row0 = blockIdx.y * BM;
    const int col0 = blockIdx.x * BN;

    auto fill = [&](int st, int k0) {
        uint32_t base = smb + st * (STG_F * 4);
#pragma unroll
        for (int j = 0; j < 4; j++) {
            int id = tid + 256 * j;           // 0..1023
            int isB = id >> 9;
            int r  = (id & 511) >> 2;         // 0..127
            int kc = id & 3;
            long long srow;
            if (isB) {
                int n = col0 + r;
                if (MODE == MODE_SILU) {
                    srow = (n >> 1) + (n & 1) * FFDIM;
                } else if (MODE == MODE_ROPE) {
                    if (n < 2048) {
                        int m = n & 1023;
                        srow = (n & 1024) + (m >> 1) + (m & 1) * 512;
                    } else srow = n;
                } else srow = n;
            } else srow = row0 + r;
            const float* src = (isB ? B + srow * ldb : A + srow * lda) + k0 + kc * 4;
            uint32_t dst = base + (isB ? B_F * 4 : 0) + r * (RS * 4) + kc * 16;
            CP_ASYNC16(dst, src);
        }
    };

    float acc[4][4][4];
#pragma unroll
    for (int mi = 0; mi < 4; mi++)
#pragma unroll
        for (int ni = 0; ni < 4; ni++)
#pragma unroll
            for (int j = 0; j < 4; j++) acc[mi][ni][j] = 0.0f;

    const int NK = K / BK;
    fill(0, 0);       CP_COMMIT();
    fill(1, BK);      CP_COMMIT();
    fill(2, 2 * BK);  CP_COMMIT();

    for (int it = 0; it < NK; it++) {
        CP_WAIT(2);
        __syncthreads();

        // prefetch next stage BEFORE compute (stage (it-1)&3 is free: all
        // warps passed the barrier => finished computing it-1)
        int nf = it + 3;
        if (nf < NK) fill(nf & (STAGES - 1), nf * BK);
        CP_COMMIT();

        const int st = it & (STAGES - 1);
        const float* sA = sm + st * STG_F;
        const float* sB = sA + B_F;
#pragma unroll
        for (int kk = 0; kk < BK; kk += 8) {
            uint32_t af[4][4], bf[4][2];
#pragma unroll
            for (int mi = 0; mi < 4; mi++) {
                int r = wm * 64 + mi * 16 + g;
                af[mi][0] = __float_as_uint(sA[r * RS + kk + tg]);
                af[mi][1] = __float_as_uint(sA[(r + 8) * RS + kk + tg]);
                af[mi][2] = __float_as_uint(sA[r * RS + kk + tg + 4]);
                af[mi][3] = __float_as_uint(sA[(r + 8) * RS + kk + tg + 4]);
            }
#pragma unroll
            for (int ni = 0; ni < 4; ni++) {
                int c = wn * 32 + ni * 8 + g;
                bf[ni][0] = __float_as_uint(sB[c * RS + kk + tg]);
                bf[ni][1] = __float_as_uint(sB[c * RS + kk + tg + 4]);
            }
#pragma unroll
            for (int mi = 0; mi < 4; mi++)
#pragma unroll
                for (int ni = 0; ni < 4; ni++)
                    mma16n8k8(acc[mi][ni], af[mi], bf[ni]);
        }
    }

    // ---- epilogue ----
#pragma unroll
    for (int mi = 0; mi < 4; mi++) {
        long long r = row0 + wm * 64 + mi * 16 + g;
#pragma unroll
        for (int ni = 0; ni < 4; ni++) {
            int c = col0 + wn * 32 + ni * 8 + tg * 2;

            if (MODE == MODE_SILU) {
                int oc = c >> 1;
                float x0 = acc[mi][ni][0], u0 = acc[mi][ni][1];
                float x1 = acc[mi][ni][2], u1 = acc[mi][ni][3];
                C[r * ldc + oc]       = round_tf32(x0 / (1.0f + expf(-x0)) * u0);
                C[(r + 8) * ldc + oc] = round_tf32(x1 / (1.0f + expf(-x1)) * u1);
                continue;
            }

            float2 v0, v1;
            v0.x = acc[mi][ni][0] * alpha;  v0.y = acc[mi][ni][1] * alpha;
            v1.x = acc[mi][ni][2] * alpha;  v1.y = acc[mi][ni][3] * alpha;

            if (MODE == MODE_ROPE) {
                if (c < 2048) {
                    int jj = (c & 1023) >> 1;
                    float freq = exp2f(-13.2877124f * ((float)jj / 512.0f));
                    int s0 = (int)(r & 1023), s1 = (int)((r + 8) & 1023);
                    float sn, cs;
                    sincosf((float)s0 * freq, &sn, &cs);
                    float a0 = v0.x * cs - v0.y * sn;
                    float b0 = v0.y * cs + v0.x * sn;
                    v0.x = a0; v0.y = b0;
                    sincosf((float)s1 * freq, &sn, &cs);
                    float a1 = v1.x * cs - v1.y * sn;
                    float b1 = v1.y * cs + v1.x * sn;
                    v1.x = a1; v1.y = b1;
                }
                v0.x = round_tf32(v0.x); v0.y = round_tf32(v0.y);
                v1.x = round_tf32(v1.x); v1.y = round_tf32(v1.y);
            }

            long long i0 = r * (long long)ldc + c;
            long long i1 = (r + 8) * (long long)ldc + c;
            if (Rp) {
                float2 r0 = *(const float2*)(Rp + i0);
                float2 r1 = *(const float2*)(Rp + i1);
                v0.x += r0.x; v0.y += r0.y;
                v1.x += r1.x; v1.y += r1.y;
            }
            if (MODE == MODE_ROUND) {
                v0.x = round_tf32(v0.x); v0.y = round_tf32(v0.y);
                v1.x = round_tf32(v1.x); v1.y = round_tf32(v1.y);
            }
            *(float2*)(C + i0) = v0;
            *(float2*)(C + i1) = v1;
        }
    }
}

// ---------------------------------------------------------------------------
// Aux kernels
// ---------------------------------------------------------------------------
__global__ void round_weights_kernel(const float* __restrict__ src,
                                     float* __restrict__ dst)
{
    long long i = ((long long)blockIdx.x * 256 + threadIdx.x) * 4;
    float4 v = *(const float4*)(src + i);
    v.x = round_tf32(v.x); v.y = round_tf32(v.y);
    v.z = round_tf32(v.z); v.w = round_tf32(v.w);
    *(float4*)(dst + i) = v;
}

__global__ void embed_kernel(const int* __restrict__ ids,
                             const float* __restrict__ embed, float* __restrict__ h)
{
    int bs = blockIdx.x;
    long long tok = ids[bs];
    const float4* src = (const float4*)(embed + tok * DIM);
    float4 v = src[threadIdx.x];
    v.x = round_tf32(v.x); v.y = round_tf32(v.y);
    v.z = round_tf32(v.z); v.w = round_tf32(v.w);
    ((float4*)(h + (long long)bs * DIM))[threadIdx.x] = v;
}

__global__ void transpose_v_kernel(const float* __restrict__ qkv, float* __restrict__ vt)
{
    __shared__ float t[32][33];
    int b = blockIdx.z;
    int s0 = blockIdx.x * 32, d0 = blockIdx.y * 32;
    int s = s0 + threadIdx.y, d = d0 + threadIdx.x;
    t[threadIdx.y][threadIdx.x] = qkv[((long long)b * SEQ + s) * 3072 + 2048 + d];
    __syncthreads();
    int dd = d0 + threadIdx.y, ss = s0 + threadIdx.x;
    vt[((long long)b * DIM + dd) * SEQ + ss] = round_tf32(t[threadIdx.x][threadIdx.y]);
}

__global__ void softmax_kernel(float* __restrict__ Sm)
{
    __shared__ float red[256];
    float* row = Sm + (long long)blockIdx.x * SEQ;
    int t = threadIdx.x;
    float4 v = ((float4*)row)[t];
    float m = fmaxf(fmaxf(v.x, v.y), fmaxf(v.z, v.w));
    red[t] = m; __syncthreads();
    for (int w = 128; w > 0; w >>= 1) { if (t < w) red[t] = fmaxf(red[t], red[t + w]); __syncthreads(); }
    m = red[0]; __syncthreads();
    float e0 = expf(v.x - m), e1 = expf(v.y - m), e2 = expf(v.z - m), e3 = expf(v.w - m);
    red[t] = e0 + e1 + e2 + e3; __syncthreads();
    for (int w = 128; w > 0; w >>= 1) { if (t < w) red[t] += red[t + w]; __syncthreads(); }
    float inv = 1.0f / red[0];
    ((float4*)row)[t] = make_float4(round_tf32(e0 * inv), round_tf32(e1 * inv),
                                    round_tf32(e2 * inv), round_tf32(e3 * inv));
}

// ---------------------------------------------------------------------------
// Host side
// ---------------------------------------------------------------------------
template<int MODE>
static void gemm(const float* A, int lda, long long sAz,
                 const float* B, int ldb, long long sBz,
                 float* C, int ldc, long long sCz,
                 const float* R, int M, int N, int K, float alpha, int bz)
{
    dim3 grid(N / BN, M / BM, bz);
    tf32_gemm<MODE><<<grid, 256, GEMM_SMEM>>>(A, lda, sAz, B, ldb, sBz,
                                              C, ldc, sCz, R, K, alpha);
}

extern "C" void kernel_launch(void* const* d_in, const int* in_sizes, int n_in,
                              void* d_out, int out_size)
{
    (void)in_sizes; (void)n_in; (void)out_size;
    const int*   ids    = (const int*)d_in[0];
    const float* blocks = (const float*)d_in[1];
    float*       out    = (float*)d_out;

    static int attr_done = 0;
    if (!attr_done) {
        cudaFuncSetAttribute(tf32_gemm<MODE_PLAIN>,
                             cudaFuncAttributeMaxDynamicSharedMemorySize, GEMM_SMEM);
        cudaFuncSetAttribute(tf32_gemm<MODE_ROUND>,
                             cudaFuncAttributeMaxDynamicSharedMemorySize, GEMM_SMEM);
        cudaFuncSetAttribute(tf32_gemm<MODE_SILU>,
                             cudaFuncAttributeMaxDynamicSharedMemorySize, GEMM_SMEM);
        cudaFuncSetAttribute(tf32_gemm<MODE_ROPE>,
                             cudaFuncAttributeMaxDynamicSharedMemorySize, GEMM_SMEM);
        attr_done = 1;
    }

    float *w, *h, *qkv, *vt, *s, *a, *t;
    cudaGetSymbolAddress((void**)&w,   g_w);
    cudaGetSymbolAddress((void**)&h,   g_h);
    cudaGetSymbolAddress((void**)&qkv, g_qkv);
    cudaGetSymbolAddress((void**)&vt,  g_vt);
    cudaGetSymbolAddress((void**)&s,   g_s);
    cudaGetSymbolAddress((void**)&a,   g_a);
    cudaGetSymbolAddress((void**)&t,   g_t);

    const long long SD3 = (long long)SEQ * 3072;
    const long long SD  = (long long)SEQ * DIM;
    const long long SS  = (long long)SEQ * SEQ;

    round_weights_kernel<<<(int)(NWEIGHT / 4 / 256), 256>>>(blocks + LAYER0_OFF, w);
    embed_kernel<<<MTOK, 256>>>(ids, blocks, h);

    for (int l = 0; l < 2; l++) {
        const float* Wqkv = w + (long long)l * LAYER_STRIDE;  // [3072,1024]
        const float* Wo   = Wqkv + 3LL * DIM * DIM;
        const float* Wgu  = Wo + (long long)DIM * DIM;        // [8192,1024]
        const float* Wd   = Wgu + 2LL * FFDIM * DIM;

        // qkv = h @ Wqkv^T, q/k pair-interleaved + RoPE in epilogue
        gemm<MODE_ROPE>(h, DIM, 0, Wqkv, DIM, 0, qkv, 3 * DIM, 0, nullptr,
                        MTOK, 3 * DIM, DIM, 1.0f, 1);
        {
            dim3 gr(SEQ / 32, DIM / 32, BATCH);
            transpose_v_kernel<<<gr, dim3(32, 32)>>>(qkv, vt);
        }
        // scores = scale * q @ k^T  (permuted-d layout; dot invariant)
        gemm<MODE_PLAIN>(qkv, 3 * DIM, SD3, qkv + 1024, 3 * DIM, SD3, s, SEQ, SS,
                         nullptr, SEQ, SEQ, DIM, 1.0f / 32.0f, BATCH);
        softmax_kernel<<<BATCH * SEQ, 256>>>(s);
        // a = attn @ V
        gemm<MODE_ROUND>(s, SEQ, SS, vt, SEQ, SD, a, DIM, SD, nullptr,
                         SEQ, DIM, SEQ, 1.0f, BATCH);
        // h = a @ Wo^T + h
        gemm<MODE_ROUND>(a, DIM, 0, Wo, DIM, 0, h, DIM, 0, h,
                         MTOK, DIM, DIM, 1.0f, 1);
        // t = silu(h@Wg^T) * (h@Wu^T)  — fused, interleaved B rows
        gemm<MODE_SILU>(h, DIM, 0, Wgu, DIM, 0, t, FFDIM, 0, nullptr,
                        MTOK, 2 * FFDIM, DIM, 1.0f, 1);
        // h = t @ Wd^T + h
        gemm<MODE_ROUND>(t, FFDIM, 0, Wd, FFDIM, 0, h, DIM, 0, h,
                         MTOK, DIM, FFDIM, 1.0f, 1);
    }

    gemm<MODE_PLAIN>(h, DIM, 0, w + 2 * LAYER_STRIDE, DIM, 0, out, VOC, 0, nullptr,
                     MTOK, VOC, DIM, 1.0f, 1);
}

// round 7
// speedup vs baseline: 1.1013x; 1.1013x over previous
#include <cuda_runtime.h>
#include <cuda_bf16.h>
#include <math.h>
#include <stdint.h>

// ---------------------------------------------------------------------------
// Model dims
// ---------------------------------------------------------------------------
#define DIM   1024
#define FFDIM 4096
#define VOC   32000
#define SEQ   1024
#define BATCH 2
#define MTOK  (BATCH * SEQ)

#define LAYER0_OFF   32768000LL
#define LAYER_STRIDE 16777216LL
#define NWEIGHT      (2 * LAYER_STRIDE + (long long)VOC * DIM)

// ---------------------------------------------------------------------------
// Scratch
// ---------------------------------------------------------------------------
__device__ float g_w  [NWEIGHT];          // tf32-rounded weights
__device__ float g_h  [MTOK * DIM];
__device__ float g_qkv[MTOK * 3 * DIM];   // q,k pair-interleaved; v plain
__device__ float g_vt [BATCH * DIM * SEQ];
__device__ float g_s  [BATCH * SEQ * SEQ];
__device__ float g_a  [MTOK * DIM];
__device__ float g_t  [MTOK * FFDIM];

// ---------------------------------------------------------------------------
// helpers
// ---------------------------------------------------------------------------
__device__ __forceinline__ uint32_t f2tf32(float x) {
    uint32_t r;
    asm("cvt.rna.tf32.f32 %0, %1;" : "=r"(r) : "f"(x));
    return r;
}
__device__ __forceinline__ float round_tf32(float x) {
    return __uint_as_float(f2tf32(x));
}
__device__ __forceinline__ uint32_t smem_u32(const void* p) {
    uint32_t a;
    asm("{ .reg .u64 t; cvta.to.shared.u64 t, %1; cvt.u32.u64 %0, t; }" : "=r"(a) : "l"(p));
    return a;
}
#define CP_ASYNC16(dst, src) \
    asm volatile("cp.async.cg.shared.global [%0], [%1], 16;" :: "r"(dst), "l"(src))
#define CP_COMMIT() asm volatile("cp.async.commit_group;" ::: "memory")
#define CP_WAIT(n)  asm volatile("cp.async.wait_group %0;" :: "n"(n) : "memory")

__device__ __forceinline__ void mma16n8k8(float c[4], const uint32_t a[4],
                                          const uint32_t b[2]) {
    asm volatile(
        "mma.sync.aligned.m16n8k8.row.col.f32.tf32.tf32.f32 "
        "{%0,%1,%2,%3}, {%4,%5,%6,%7}, {%8,%9}, {%0,%1,%2,%3};"
        : "+f"(c[0]), "+f"(c[1]), "+f"(c[2]), "+f"(c[3])
        : "r"(a[0]), "r"(a[1]), "r"(a[2]), "r"(a[3]), "r"(b[0]), "r"(b[1]));
}

// ---------------------------------------------------------------------------
// tf32 GEMM, cp.async 4-stage, 128 threads, 4 warps (2Mx2N), warp tile 64x64.
// C[M,N] = alpha*A@B^T (+R). Modes: PLAIN / ROUND / SILU / ROPE.
// ---------------------------------------------------------------------------
#define MODE_PLAIN 0
#define MODE_ROUND 1
#define MODE_SILU  2
#define MODE_ROPE  3

#define BM 128
#define BN 128
#define BK 16
#define RS 20
#define STG_F   (2 * 128 * RS)
#define B_F     (128 * RS)
#define STAGES  4
#define GEMM_SMEM (STAGES * STG_F * 4)

template<int MODE>
__global__ __launch_bounds__(128, 2)
void tf32_gemm(const float* __restrict__ A, int lda, long long sAz,
               const float* __restrict__ B, int ldb, long long sBz,
               float* __restrict__ C, int ldc, long long sCz,
               const float* __restrict__ R, int K, float alpha)
{
    extern __shared__ float sm[];
    const uint32_t smb = smem_u32(sm);

    const int tid  = threadIdx.x;
    const int warp = tid >> 5, lane = tid & 31;
    const int wm = warp & 1;          // 2 M halves
    const int wn = warp >> 1;         // 2 N halves
    const int g  = lane >> 2;
    const int tg = lane & 3;

    const long long bz = blockIdx.z;
    A += bz * sAz;  B += bz * sBz;  C += bz * sCz;
    const float* Rp = R ? (R + bz * sCz) : nullptr;
    const int row0 = blockIdx.y * BM;
    const int col0 = blockIdx.x * BN;

    auto fill = [&](int st, int k0) {
        uint32_t base = smb + st * (STG_F * 4);
#pragma unroll
        for (int j = 0; j < 8; j++) {
            int id = tid + 128 * j;           // 0..1023
            int isB = id >> 9;
            int r  = (id & 511) >> 2;         // 0..127
            int kc = id & 3;
            long long srow;
            if (isB) {
                int n = col0 + r;
                if (MODE == MODE_SILU) {
                    srow = (n >> 1) + (n & 1) * FFDIM;
                } else if (MODE == MODE_ROPE) {
                    if (n < 2048) {
                        int m = n & 1023;
                        srow = (n & 1024) + (m >> 1) + (m & 1) * 512;
                    } else srow = n;
                } else srow = n;
            } else srow = row0 + r;
            const float* src = (isB ? B + srow * ldb : A + srow * lda) + k0 + kc * 4;
            uint32_t dst = base + (isB ? B_F * 4 : 0) + r * (RS * 4) + kc * 16;
            CP_ASYNC16(dst, src);
        }
    };

    float acc[4][8][4];
#pragma unroll
    for (int mi = 0; mi < 4; mi++)
#pragma unroll
        for (int ni = 0; ni < 8; ni++)
#pragma unroll
            for (int j = 0; j < 4; j++) acc[mi][ni][j] = 0.0f;

    const int NK = K / BK;
    fill(0, 0);       CP_COMMIT();
    fill(1, BK);      CP_COMMIT();
    fill(2, 2 * BK);  CP_COMMIT();

    for (int it = 0; it < NK; it++) {
        CP_WAIT(2);
        __syncthreads();

        const int st = it & (STAGES - 1);
        const float* sA = sm + st * STG_F;
        const float* sB = sA + B_F;
#pragma unroll
        for (int kk = 0; kk < BK; kk += 8) {
            uint32_t af[4][4], bf[8][2];
#pragma unroll
            for (int mi = 0; mi < 4; mi++) {
                int r = wm * 64 + mi * 16 + g;
                af[mi][0] = __float_as_uint(sA[r * RS + kk + tg]);
                af[mi][1] = __float_as_uint(sA[(r + 8) * RS + kk + tg]);
                af[mi][2] = __float_as_uint(sA[r * RS + kk + tg + 4]);
                af[mi][3] = __float_as_uint(sA[(r + 8) * RS + kk + tg + 4]);
            }
#pragma unroll
            for (int ni = 0; ni < 8; ni++) {
                int c = wn * 64 + ni * 8 + g;
                bf[ni][0] = __float_as_uint(sB[c * RS + kk + tg]);
                bf[ni][1] = __float_as_uint(sB[c * RS + kk + tg + 4]);
            }
#pragma unroll
            for (int mi = 0; mi < 4; mi++)
#pragma unroll
                for (int ni = 0; ni < 8; ni++)
                    mma16n8k8(acc[mi][ni], af[mi], bf[ni]);
        }

        int nf = it + 3;
        if (nf < NK) fill(nf & (STAGES - 1), nf * BK);
        CP_COMMIT();
    }

    // ---- epilogue ----
#pragma unroll
    for (int mi = 0; mi < 4; mi++) {
        long long r = row0 + wm * 64 + mi * 16 + g;
#pragma unroll
        for (int ni = 0; ni < 8; ni++) {
            int c = col0 + wn * 64 + ni * 8 + tg * 2;

            if (MODE == MODE_SILU) {
                int oc = c >> 1;
                float x0 = acc[mi][ni][0], u0 = acc[mi][ni][1];
                float x1 = acc[mi][ni][2], u1 = acc[mi][ni][3];
                C[r * ldc + oc]       = round_tf32(x0 / (1.0f + expf(-x0)) * u0);
                C[(r + 8) * ldc + oc] = round_tf32(x1 / (1.0f + expf(-x1)) * u1);
                continue;
            }

            float2 v0, v1;
            v0.x = acc[mi][ni][0] * alpha;  v0.y = acc[mi][ni][1] * alpha;
            v1.x = acc[mi][ni][2] * alpha;  v1.y = acc[mi][ni][3] * alpha;

            if (MODE == MODE_ROPE) {
                if (c < 2048) {
                    int jj = (c & 1023) >> 1;
                    float freq = exp2f(-13.2877124f * ((float)jj / 512.0f));
                    int s0 = (int)(r & 1023), s1 = (int)((r + 8) & 1023);
                    float sn, cs;
                    sincosf((float)s0 * freq, &sn, &cs);
                    float a0 = v0.x * cs - v0.y * sn;
                    float b0 = v0.y * cs + v0.x * sn;
                    v0.x = a0; v0.y = b0;
                    sincosf((float)s1 * freq, &sn, &cs);
                    float a1 = v1.x * cs - v1.y * sn;
                    float b1 = v1.y * cs + v1.x * sn;
                    v1.x = a1; v1.y = b1;
                }
                v0.x = round_tf32(v0.x); v0.y = round_tf32(v0.y);
                v1.x = round_tf32(v1.x); v1.y = round_tf32(v1.y);
            }

            long long i0 = r * (long long)ldc + c;
            long long i1 = (r + 8) * (long long)ldc + c;
            if (Rp) {
                float2 r0 = *(const float2*)(Rp + i0);
                float2 r1 = *(const float2*)(Rp + i1);
                v0.x += r0.x; v0.y += r0.y;
                v1.x += r1.x; v1.y += r1.y;
            }
            if (MODE == MODE_ROUND) {
                v0.x = round_tf32(v0.x); v0.y = round_tf32(v0.y);
                v1.x = round_tf32(v1.x); v1.y = round_tf32(v1.y);
            }
            *(float2*)(C + i0) = v0;
            *(float2*)(C + i1) = v1;
        }
    }
}

// ---------------------------------------------------------------------------
// Aux kernels
// ---------------------------------------------------------------------------
__global__ void round_weights_kernel(const float* __restrict__ src,
                                     float* __restrict__ dst)
{
    long long i = ((long long)blockIdx.x * 256 + threadIdx.x) * 4;
    float4 v = *(const float4*)(src + i);
    v.x = round_tf32(v.x); v.y = round_tf32(v.y);
    v.z = round_tf32(v.z); v.w = round_tf32(v.w);
    *(float4*)(dst + i) = v;
}

__global__ void embed_kernel(const int* __restrict__ ids,
                             const float* __restrict__ embed, float* __restrict__ h)
{
    int bs = blockIdx.x;
    long long tok = ids[bs];
    const float4* src = (const float4*)(embed + tok * DIM);
    float4 v = src[threadIdx.x];
    v.x = round_tf32(v.x); v.y = round_tf32(v.y);
    v.z = round_tf32(v.z); v.w = round_tf32(v.w);
    ((float4*)(h + (long long)bs * DIM))[threadIdx.x] = v;
}

__global__ void transpose_v_kernel(const float* __restrict__ qkv, float* __restrict__ vt)
{
    __shared__ float t[32][33];
    int b = blockIdx.z;
    int s0 = blockIdx.x * 32, d0 = blockIdx.y * 32;
    int s = s0 + threadIdx.y, d = d0 + threadIdx.x;
    t[threadIdx.y][threadIdx.x] = qkv[((long long)b * SEQ + s) * 3072 + 2048 + d];
    __syncthreads();
    int dd = d0 + threadIdx.y, ss = s0 + threadIdx.x;
    vt[((long long)b * DIM + dd) * SEQ + ss] = round_tf32(t[threadIdx.x][threadIdx.y]);
}

__global__ void softmax_kernel(float* __restrict__ Sm)
{
    __shared__ float red[256];
    float* row = Sm + (long long)blockIdx.x * SEQ;
    int t = threadIdx.x;
    float4 v = ((float4*)row)[t];
    float m = fmaxf(fmaxf(v.x, v.y), fmaxf(v.z, v.w));
    red[t] = m; __syncthreads();
    for (int w = 128; w > 0; w >>= 1) { if (t < w) red[t] = fmaxf(red[t], red[t + w]); __syncthreads(); }
    m = red[0]; __syncthreads();
    float e0 = expf(v.x - m), e1 = expf(v.y - m), e2 = expf(v.z - m), e3 = expf(v.w - m);
    red[t] = e0 + e1 + e2 + e3; __syncthreads();
    for (int w = 128; w > 0; w >>= 1) { if (t < w) red[t] += red[t + w]; __syncthreads(); }
    float inv = 1.0f / red[0];
    ((float4*)row)[t] = make_float4(round_tf32(e0 * inv), round_tf32(e1 * inv),
                                    round_tf32(e2 * inv), round_tf32(e3 * inv));
}

// ---------------------------------------------------------------------------
// Host side
// ---------------------------------------------------------------------------
template<int MODE>
static void gemm(const float* A, int lda, long long sAz,
                 const float* B, int ldb, long long sBz,
                 float* C, int ldc, long long sCz,
                 const float* R, int M, int N, int K, float alpha, int bz)
{
    dim3 grid(N / BN, M / BM, bz);
    tf32_gemm<MODE><<<grid, 128, GEMM_SMEM>>>(A, lda, sAz, B, ldb, sBz,
                                              C, ldc, sCz, R, K, alpha);
}

extern "C" void kernel_launch(void* const* d_in, const int* in_sizes, int n_in,
                              void* d_out, int out_size)
{
    (void)in_sizes; (void)n_in; (void)out_size;
    const int*   ids    = (const int*)d_in[0];
    const float* blocks = (const float*)d_in[1];
    float*       out    = (float*)d_out;

    static int attr_done = 0;
    if (!attr_done) {
        cudaFuncSetAttribute(tf32_gemm<MODE_PLAIN>,
                             cudaFuncAttributeMaxDynamicSharedMemorySize, GEMM_SMEM);
        cudaFuncSetAttribute(tf32_gemm<MODE_ROUND>,
                             cudaFuncAttributeMaxDynamicSharedMemorySize, GEMM_SMEM);
        cudaFuncSetAttribute(tf32_gemm<MODE_SILU>,
                             cudaFuncAttributeMaxDynamicSharedMemorySize, GEMM_SMEM);
        cudaFuncSetAttribute(tf32_gemm<MODE_ROPE>,
                             cudaFuncAttributeMaxDynamicSharedMemorySize, GEMM_SMEM);
        attr_done = 1;
    }

    float *w, *h, *qkv, *vt, *s, *a, *t;
    cudaGetSymbolAddress((void**)&w,   g_w);
    cudaGetSymbolAddress((void**)&h,   g_h);
    cudaGetSymbolAddress((void**)&qkv, g_qkv);
    cudaGetSymbolAddress((void**)&vt,  g_vt);
    cudaGetSymbolAddress((void**)&s,   g_s);
    cudaGetSymbolAddress((void**)&a,   g_a);
    cudaGetSymbolAddress((void**)&t,   g_t);

    const long long SD3 = (long long)SEQ * 3072;
    const long long SD  = (long long)SEQ * DIM;
    const long long SS  = (long long)SEQ * SEQ;

    round_weights_kernel<<<(int)(NWEIGHT / 4 / 256), 256>>>(blocks + LAYER0_OFF, w);
    embed_kernel<<<MTOK, 256>>>(ids, blocks, h);

    for (int l = 0; l < 2; l++) {
        const float* Wqkv = w + (long long)l * LAYER_STRIDE;  // [3072,1024]
        const float* Wo   = Wqkv + 3LL * DIM * DIM;
        const float* Wgu  = Wo + (long long)DIM * DIM;        // [8192,1024]
        const float* Wd   = Wgu + 2LL * FFDIM * DIM;

        // qkv = h @ Wqkv^T, q/k pair-interleaved + RoPE in epilogue
        gemm<MODE_ROPE>(h, DIM, 0, Wqkv, DIM, 0, qkv, 3 * DIM, 0, nullptr,
                        MTOK, 3 * DIM, DIM, 1.0f, 1);
        {
            dim3 gr(SEQ / 32, DIM / 32, BATCH);
            transpose_v_kernel<<<gr, dim3(32, 32)>>>(qkv, vt);
        }
        // scores = scale * q @ k^T (permuted-d layout; dot invariant)
        gemm<MODE_PLAIN>(qkv, 3 * DIM, SD3, qkv + 1024, 3 * DIM, SD3, s, SEQ, SS,
                         nullptr, SEQ, SEQ, DIM, 1.0f / 32.0f, BATCH);
        softmax_kernel<<<BATCH * SEQ, 256>>>(s);
        // a = attn @ V
        gemm<MODE_ROUND>(s, SEQ, SS, vt, SEQ, SD, a, DIM, SD, nullptr,
                         SEQ, DIM, SEQ, 1.0f, BATCH);
        // h = a @ Wo^T + h
        gemm<MODE_ROUND>(a, DIM, 0, Wo, DIM, 0, h, DIM, 0, h,
                         MTOK, DIM, DIM, 1.0f, 1);
        // t = silu(h@Wg^T) * (h@Wu^T)  — fused, interleaved B rows
        gemm<MODE_SILU>(h, DIM, 0, Wgu, DIM, 0, t, FFDIM, 0, nullptr,
                        MTOK, 2 * FFDIM, DIM, 1.0f, 1);
        // h = t @ Wd^T + h
        gemm<MODE_ROUND>(t, FFDIM, 0, Wd, FFDIM, 0, h, DIM, 0, h,
                         MTOK, DIM, FFDIM, 1.0f, 1);
    }

    gemm<MODE_PLAIN>(h, DIM, 0, w + 2 * LAYER_STRIDE, DIM, 0, out, VOC, 0, nullptr,
                     MTOK, VOC, DIM, 1.0f, 1);
}

// round 8
// speedup vs baseline: 1.1494x; 1.0437x over previous
#include <cuda_runtime.h>
#include <cuda_bf16.h>
#include <math.h>
#include <stdint.h>

// ---------------------------------------------------------------------------
// Model dims
// ---------------------------------------------------------------------------
#define DIM   1024
#define FFDIM 4096
#define VOC   32000
#define SEQ   1024
#define BATCH 2
#define MTOK  (BATCH * SEQ)

#define LAYER0_OFF   32768000LL
#define LAYER_STRIDE 16777216LL
#define NWEIGHT      (2 * LAYER_STRIDE + (long long)VOC * DIM)

// ---------------------------------------------------------------------------
// Scratch
// ---------------------------------------------------------------------------
__device__ float g_w   [NWEIGHT];          // tf32-rounded weights
__device__ float g_h   [MTOK * DIM];
__device__ float g_qkv [MTOK * 3 * DIM];   // q,k pair-interleaved; v plain
__device__ float g_vt  [BATCH * DIM * SEQ];
__device__ float g_s   [BATCH * SEQ * SEQ];
__device__ float g_a   [MTOK * DIM];
__device__ float g_t   [MTOK * FFDIM];
__device__ float g_part[2 * MTOK * DIM];   // split-K partials (2 x 2M floats)

// ---------------------------------------------------------------------------
// helpers
// ---------------------------------------------------------------------------
__device__ __forceinline__ uint32_t f2tf32(float x) {
    uint32_t r;
    asm("cvt.rna.tf32.f32 %0, %1;" : "=r"(r) : "f"(x));
    return r;
}
__device__ __forceinline__ float round_tf32(float x) {
    return __uint_as_float(f2tf32(x));
}
__device__ __forceinline__ uint32_t smem_u32(const void* p) {
    uint32_t a;
    asm("{ .reg .u64 t; cvta.to.shared.u64 t, %1; cvt.u32.u64 %0, t; }" : "=r"(a) : "l"(p));
    return a;
}
#define CP_ASYNC16(dst, src) \
    asm volatile("cp.async.cg.shared.global [%0], [%1], 16;" :: "r"(dst), "l"(src))
#define CP_COMMIT() asm volatile("cp.async.commit_group;" ::: "memory")
#define CP_WAIT(n)  asm volatile("cp.async.wait_group %0;" :: "n"(n) : "memory")

__device__ __forceinline__ void mma16n8k8(float c[4], const uint32_t a[4],
                                          const uint32_t b[2]) {
    asm volatile(
        "mma.sync.aligned.m16n8k8.row.col.f32.tf32.tf32.f32 "
        "{%0,%1,%2,%3}, {%4,%5,%6,%7}, {%8,%9}, {%0,%1,%2,%3};"
        : "+f"(c[0]), "+f"(c[1]), "+f"(c[2]), "+f"(c[3])
        : "r"(a[0]), "r"(a[1]), "r"(a[2]), "r"(a[3]), "r"(b[0]), "r"(b[1]));
}

// ---------------------------------------------------------------------------
// tf32 GEMM, cp.async 4-stage, 128 threads, 4 warps (2Mx2N), warp tile 64x64.
// C[M,N] = alpha*A@B^T (+R). Modes: PLAIN / ROUND / SILU / ROPE.
// Optional split-K (SK=2): grid.z = bz*2, K is the K-slice, partial written
// to C + sk*sSkz (use MODE_PLAIN, alpha=1, R=null).
// ---------------------------------------------------------------------------
#define MODE_PLAIN 0
#define MODE_ROUND 1
#define MODE_SILU  2
#define MODE_ROPE  3

#define BM 128
#define BN 128
#define BK 16
#define RS 20
#define STG_F   (2 * 128 * RS)
#define B_F     (128 * RS)
#define STAGES  4
#define GEMM_SMEM (STAGES * STG_F * 4)

template<int MODE>
__global__ __launch_bounds__(128, 2)
void tf32_gemm(const float* __restrict__ A, int lda, long long sAz,
               const float* __restrict__ B, int ldb, long long sBz,
               float* __restrict__ C, int ldc, long long sCz,
               const float* __restrict__ R, int K, float alpha,
               int SK, long long sSkz)
{
    extern __shared__ float sm[];
    const uint32_t smb = smem_u32(sm);

    const int tid  = threadIdx.x;
    const int warp = tid >> 5, lane = tid & 31;
    const int wm = warp & 1;
    const int wn = warp >> 1;
    const int g  = lane >> 2;
    const int tg = lane & 3;

    int bzr = blockIdx.z;
    int sk = 0;
    if (SK == 2) { sk = bzr & 1; bzr >>= 1; }
    const long long bz = bzr;
    A += bz * sAz + (long long)sk * K;
    B += bz * sBz + (long long)sk * K;
    C += bz * sCz + (long long)sk * sSkz;
    const float* Rp = R ? (R + bz * sCz) : nullptr;
    const int row0 = blockIdx.y * BM;
    const int col0 = blockIdx.x * BN;

    auto fill = [&](int st, int k0) {
        uint32_t base = smb + st * (STG_F * 4);
#pragma unroll
        for (int j = 0; j < 8; j++) {
            int id = tid + 128 * j;           // 0..1023
            int isB = id >> 9;
            int r  = (id & 511) >> 2;         // 0..127
            int kc = id & 3;
            long long srow;
            if (isB) {
                int n = col0 + r;
                if (MODE == MODE_SILU) {
                    srow = (n >> 1) + (n & 1) * FFDIM;
                } else if (MODE == MODE_ROPE) {
                    if (n < 2048) {
                        int m = n & 1023;
                        srow = (n & 1024) + (m >> 1) + (m & 1) * 512;
                    } else srow = n;
                } else srow = n;
            } else srow = row0 + r;
            const float* src = (isB ? B + srow * ldb : A + srow * lda) + k0 + kc * 4;
            uint32_t dst = base + (isB ? B_F * 4 : 0) + r * (RS * 4) + kc * 16;
            CP_ASYNC16(dst, src);
        }
    };

    float acc[4][8][4];
#pragma unroll
    for (int mi = 0; mi < 4; mi++)
#pragma unroll
        for (int ni = 0; ni < 8; ni++)
#pragma unroll
            for (int j = 0; j < 4; j++) acc[mi][ni][j] = 0.0f;

    const int NK = K / BK;
    fill(0, 0);       CP_COMMIT();
    fill(1, BK);      CP_COMMIT();
    fill(2, 2 * BK);  CP_COMMIT();

    for (int it = 0; it < NK; it++) {
        CP_WAIT(2);
        __syncthreads();

        const int st = it & (STAGES - 1);
        const float* sA = sm + st * STG_F;
        const float* sB = sA + B_F;
#pragma unroll
        for (int kk = 0; kk < BK; kk += 8) {
            uint32_t af[4][4], bf[8][2];
#pragma unroll
            for (int mi = 0; mi < 4; mi++) {
                int r = wm * 64 + mi * 16 + g;
                af[mi][0] = __float_as_uint(sA[r * RS + kk + tg]);
                af[mi][1] = __float_as_uint(sA[(r + 8) * RS + kk + tg]);
                af[mi][2] = __float_as_uint(sA[r * RS + kk + tg + 4]);
                af[mi][3] = __float_as_uint(sA[(r + 8) * RS + kk + tg + 4]);
            }
#pragma unroll
            for (int ni = 0; ni < 8; ni++) {
                int c = wn * 64 + ni * 8 + g;
                bf[ni][0] = __float_as_uint(sB[c * RS + kk + tg]);
                bf[ni][1] = __float_as_uint(sB[c * RS + kk + tg + 4]);
            }
#pragma unroll
            for (int mi = 0; mi < 4; mi++)
#pragma unroll
                for (int ni = 0; ni < 8; ni++)
                    mma16n8k8(acc[mi][ni], af[mi], bf[ni]);
        }

        int nf = it + 3;
        if (nf < NK) fill(nf & (STAGES - 1), nf * BK);
        CP_COMMIT();
    }

    // ---- epilogue ----
#pragma unroll
    for (int mi = 0; mi < 4; mi++) {
        long long r = row0 + wm * 64 + mi * 16 + g;
#pragma unroll
        for (int ni = 0; ni < 8; ni++) {
            int c = col0 + wn * 64 + ni * 8 + tg * 2;

            if (MODE == MODE_SILU) {
                int oc = c >> 1;
                float x0 = acc[mi][ni][0], u0 = acc[mi][ni][1];
                float x1 = acc[mi][ni][2], u1 = acc[mi][ni][3];
                C[r * ldc + oc]       = round_tf32(x0 / (1.0f + expf(-x0)) * u0);
                C[(r + 8) * ldc + oc] = round_tf32(x1 / (1.0f + expf(-x1)) * u1);
                continue;
            }

            float2 v0, v1;
            v0.x = acc[mi][ni][0] * alpha;  v0.y = acc[mi][ni][1] * alpha;
            v1.x = acc[mi][ni][2] * alpha;  v1.y = acc[mi][ni][3] * alpha;

            if (MODE == MODE_ROPE) {
                if (c < 2048) {
                    int jj = (c & 1023) >> 1;
                    float freq = exp2f(-13.2877124f * ((float)jj / 512.0f));
                    int s0 = (int)(r & 1023), s1 = (int)((r + 8) & 1023);
                    float sn, cs;
                    sincosf((float)s0 * freq, &sn, &cs);
                    float a0 = v0.x * cs - v0.y * sn;
                    float b0 = v0.y * cs + v0.x * sn;
                    v0.x = a0; v0.y = b0;
                    sincosf((float)s1 * freq, &sn, &cs);
                    float a1 = v1.x * cs - v1.y * sn;
                    float b1 = v1.y * cs + v1.x * sn;
                    v1.x = a1; v1.y = b1;
                }
                v0.x = round_tf32(v0.x); v0.y = round_tf32(v0.y);
                v1.x = round_tf32(v1.x); v1.y = round_tf32(v1.y);
            }

            long long i0 = r * (long long)ldc + c;
            long long i1 = (r + 8) * (long long)ldc + c;
            if (Rp) {
                float2 r0 = *(const float2*)(Rp + i0);
                float2 r1 = *(const float2*)(Rp + i1);
                v0.x += r0.x; v0.y += r0.y;
                v1.x += r1.x; v1.y += r1.y;
            }
            if (MODE == MODE_ROUND) {
                v0.x = round_tf32(v0.x); v0.y = round_tf32(v0.y);
                v1.x = round_tf32(v1.x); v1.y = round_tf32(v1.y);
            }
            *(float2*)(C + i0) = v0;
            *(float2*)(C + i1) = v1;
        }
    }
}

// ---------------------------------------------------------------------------
// Split-K reduce: out = round(p0 + p1 (+ R))
// ---------------------------------------------------------------------------
__global__ void reduce_round_kernel(const float* __restrict__ part, long long skStride,
                                    const float* __restrict__ R, float* __restrict__ out)
{
    long long i = ((long long)blockIdx.x * 256 + threadIdx.x) * 4;
    float4 p0 = *(const float4*)(part + i);
    float4 p1 = *(const float4*)(part + skStride + i);
    float4 v;
    v.x = p0.x + p1.x; v.y = p0.y + p1.y;
    v.z = p0.z + p1.z; v.w = p0.w + p1.w;
    if (R) {
        float4 r4 = *(const float4*)(R + i);
        v.x += r4.x; v.y += r4.y; v.z += r4.z; v.w += r4.w;
    }
    v.x = round_tf32(v.x); v.y = round_tf32(v.y);
    v.z = round_tf32(v.z); v.w = round_tf32(v.w);
    *(float4*)(out + i) = v;
}

// ---------------------------------------------------------------------------
// Aux kernels
// ---------------------------------------------------------------------------
__global__ void round_weights_kernel(const float* __restrict__ src,
                                     float* __restrict__ dst)
{
    long long i = ((long long)blockIdx.x * 256 + threadIdx.x) * 4;
    float4 v = *(const float4*)(src + i);
    v.x = round_tf32(v.x); v.y = round_tf32(v.y);
    v.z = round_tf32(v.z); v.w = round_tf32(v.w);
    *(float4*)(dst + i) = v;
}

__global__ void embed_kernel(const int* __restrict__ ids,
                             const float* __restrict__ embed, float* __restrict__ h)
{
    int bs = blockIdx.x;
    long long tok = ids[bs];
    const float4* src = (const float4*)(embed + tok * DIM);
    float4 v = src[threadIdx.x];
    v.x = round_tf32(v.x); v.y = round_tf32(v.y);
    v.z = round_tf32(v.z); v.w = round_tf32(v.w);
    ((float4*)(h + (long long)bs * DIM))[threadIdx.x] = v;
}

__global__ void transpose_v_kernel(const float* __restrict__ qkv, float* __restrict__ vt)
{
    __shared__ float t[32][33];
    int b = blockIdx.z;
    int s0 = blockIdx.x * 32, d0 = blockIdx.y * 32;
    int s = s0 + threadIdx.y, d = d0 + threadIdx.x;
    t[threadIdx.y][threadIdx.x] = qkv[((long long)b * SEQ + s) * 3072 + 2048 + d];
    __syncthreads();
    int dd = d0 + threadIdx.y, ss = s0 + threadIdx.x;
    vt[((long long)b * DIM + dd) * SEQ + ss] = round_tf32(t[threadIdx.x][threadIdx.y]);
}

// softmax over (p0+p1)*scale rows; writes rounded probs
__global__ void softmax_split_kernel(const float* __restrict__ part, long long skStride,
                                     float* __restrict__ Sm, float scale)
{
    __shared__ float red[256];
    long long row = blockIdx.x;
    const float* r0 = part + row * SEQ;
    const float* r1 = r0 + skStride;
    int t = threadIdx.x;
    float4 a = ((const float4*)r0)[t];
    float4 b = ((const float4*)r1)[t];
    float4 v;
    v.x = (a.x + b.x) * scale; v.y = (a.y + b.y) * scale;
    v.z = (a.z + b.z) * scale; v.w = (a.w + b.w) * scale;

    float m = fmaxf(fmaxf(v.x, v.y), fmaxf(v.z, v.w));
    red[t] = m; __syncthreads();
    for (int w = 128; w > 0; w >>= 1) { if (t < w) red[t] = fmaxf(red[t], red[t + w]); __syncthreads(); }
    m = red[0]; __syncthreads();
    float e0 = expf(v.x - m), e1 = expf(v.y - m), e2 = expf(v.z - m), e3 = expf(v.w - m);
    red[t] = e0 + e1 + e2 + e3; __syncthreads();
    for (int w = 128; w > 0; w >>= 1) { if (t < w) red[t] += red[t + w]; __syncthreads(); }
    float inv = 1.0f / red[0];
    float* out = Sm + row * SEQ;
    ((float4*)out)[t] = make_float4(round_tf32(e0 * inv), round_tf32(e1 * inv),
                                    round_tf32(e2 * inv), round_tf32(e3 * inv));
}

// ---------------------------------------------------------------------------
// Host side
// ---------------------------------------------------------------------------
template<int MODE>
static void gemm(const float* A, int lda, long long sAz,
                 const float* B, int ldb, long long sBz,
                 float* C, int ldc, long long sCz,
                 const float* R, int M, int N, int K, float alpha, int bz,
                 int SK = 1, long long sSkz = 0)
{
    dim3 grid(N / BN, M / BM, bz * SK);
    tf32_gemm<MODE><<<grid, 128, GEMM_SMEM>>>(A, lda, sAz, B, ldb, sBz,
                                              C, ldc, sCz, R, K / SK, alpha,
                                              SK, sSkz);
}

extern "C" void kernel_launch(void* const* d_in, const int* in_sizes, int n_in,
                              void* d_out, int out_size)
{
    (void)in_sizes; (void)n_in; (void)out_size;
    const int*   ids    = (const int*)d_in[0];
    const float* blocks = (const float*)d_in[1];
    float*       out    = (float*)d_out;

    static int attr_done = 0;
    if (!attr_done) {
        cudaFuncSetAttribute(tf32_gemm<MODE_PLAIN>,
                             cudaFuncAttributeMaxDynamicSharedMemorySize, GEMM_SMEM);
        cudaFuncSetAttribute(tf32_gemm<MODE_ROUND>,
                             cudaFuncAttributeMaxDynamicSharedMemorySize, GEMM_SMEM);
        cudaFuncSetAttribute(tf32_gemm<MODE_SILU>,
                             cudaFuncAttributeMaxDynamicSharedMemorySize, GEMM_SMEM);
        cudaFuncSetAttribute(tf32_gemm<MODE_ROPE>,
                             cudaFuncAttributeMaxDynamicSharedMemorySize, GEMM_SMEM);
        attr_done = 1;
    }

    float *w, *h, *qkv, *vt, *s, *a, *t, *part;
    cudaGetSymbolAddress((void**)&w,    g_w);
    cudaGetSymbolAddress((void**)&h,    g_h);
    cudaGetSymbolAddress((void**)&qkv,  g_qkv);
    cudaGetSymbolAddress((void**)&vt,   g_vt);
    cudaGetSymbolAddress((void**)&s,    g_s);
    cudaGetSymbolAddress((void**)&a,    g_a);
    cudaGetSymbolAddress((void**)&t,    g_t);
    cudaGetSymbolAddress((void**)&part, g_part);

    const long long SD3 = (long long)SEQ * 3072;
    const long long SD  = (long long)SEQ * DIM;
    const long long SS  = (long long)SEQ * SEQ;
    const long long SKS = (long long)MTOK * DIM;   // split-k partial stride (2M)
    const int RED_GRID  = (int)(SKS / 4 / 256);    // 2048

    round_weights_kernel<<<(int)(NWEIGHT / 4 / 256), 256>>>(blocks + LAYER0_OFF, w);
    embed_kernel<<<MTOK, 256>>>(ids, blocks, h);

    for (int l = 0; l < 2; l++) {
        const float* Wqkv = w + (long long)l * LAYER_STRIDE;  // [3072,1024]
        const float* Wo   = Wqkv + 3LL * DIM * DIM;
        const float* Wgu  = Wo + (long long)DIM * DIM;        // [8192,1024]
        const float* Wd   = Wgu + 2LL * FFDIM * DIM;

        // qkv = h @ Wqkv^T, q/k pair-interleaved + RoPE in epilogue
        gemm<MODE_ROPE>(h, DIM, 0, Wqkv, DIM, 0, qkv, 3 * DIM, 0, nullptr,
                        MTOK, 3 * DIM, DIM, 1.0f, 1);
        {
            dim3 gr(SEQ / 32, DIM / 32, BATCH);
            transpose_v_kernel<<<gr, dim3(32, 32)>>>(qkv, vt);
        }
        // scores partial = q @ k^T (split-K=2); softmax fuses reduce+scale
        gemm<MODE_PLAIN>(qkv, 3 * DIM, SD3, qkv + 1024, 3 * DIM, SD3,
                         part, SEQ, SS, nullptr, SEQ, SEQ, DIM, 1.0f, BATCH,
                         2, SKS);
        softmax_split_kernel<<<BATCH * SEQ, 256>>>(part, SKS, s, 1.0f / 32.0f);
        // a = attn @ V (split-K=2 + reduce)
        gemm<MODE_PLAIN>(s, SEQ, SS, vt, SEQ, SD, part, DIM, SD, nullptr,
                         SEQ, DIM, SEQ, 1.0f, BATCH, 2, SKS);
        reduce_round_kernel<<<RED_GRID, 256>>>(part, SKS, nullptr, a);
        // h = a @ Wo^T + h (split-K=2 + reduce w/ residual)
        gemm<MODE_PLAIN>(a, DIM, 0, Wo, DIM, 0, part, DIM, 0, nullptr,
                         MTOK, DIM, DIM, 1.0f, 1, 2, SKS);
        reduce_round_kernel<<<RED_GRID, 256>>>(part, SKS, h, h);
        // t = silu(h@Wg^T) * (h@Wu^T)  — fused, interleaved B rows
        gemm<MODE_SILU>(h, DIM, 0, Wgu, DIM, 0, t, FFDIM, 0, nullptr,
                        MTOK, 2 * FFDIM, DIM, 1.0f, 1);
        // h = t @ Wd^T + h (split-K=2 + reduce w/ residual)
        gemm<MODE_PLAIN>(t, FFDIM, 0, Wd, FFDIM, 0, part, DIM, 0, nullptr,
                         MTOK, DIM, FFDIM, 1.0f, 1, 2, SKS);
        reduce_round_kernel<<<RED_GRID, 256>>>(part, SKS, h, h);
    }

    gemm<MODE_PLAIN>(h, DIM, 0, w + 2 * LAYER_STRIDE, DIM, 0, out, VOC, 0, nullptr,
                     MTOK, VOC, DIM, 1.0f, 1);
}

// round 9
// speedup vs baseline: 1.1987x; 1.0429x over previous
#include <cuda_runtime.h>
#include <cuda_bf16.h>
#include <math.h>
#include <stdint.h>

// ---------------------------------------------------------------------------
// Model dims
// ---------------------------------------------------------------------------
#define DIM   1024
#define FFDIM 4096
#define VOC   32000
#define SEQ   1024
#define BATCH 2
#define MTOK  (BATCH * SEQ)

#define LAYER0_OFF   32768000LL
#define LAYER_STRIDE 16777216LL
#define NWEIGHT      (2 * LAYER_STRIDE + (long long)VOC * DIM)

// ---------------------------------------------------------------------------
// Scratch
// ---------------------------------------------------------------------------
__device__ float g_w   [NWEIGHT];          // tf32-rounded weights
__device__ float g_h   [MTOK * DIM];
__device__ float g_qkv [MTOK * 3 * DIM];   // q,k pair-interleaved; v plain
__device__ float g_vt  [BATCH * DIM * SEQ];
__device__ float g_s   [BATCH * SEQ * SEQ];
__device__ float g_a   [MTOK * DIM];
__device__ float g_t   [MTOK * FFDIM];
__device__ float g_part[2 * MTOK * DIM];   // split-K partials

// ---------------------------------------------------------------------------
// helpers
// ---------------------------------------------------------------------------
__device__ __forceinline__ uint32_t f2tf32(float x) {
    uint32_t r;
    asm("cvt.rna.tf32.f32 %0, %1;" : "=r"(r) : "f"(x));
    return r;
}
__device__ __forceinline__ float round_tf32(float x) {
    return __uint_as_float(f2tf32(x));
}
__device__ __forceinline__ uint32_t smem_u32(const void* p) {
    uint32_t a;
    asm("{ .reg .u64 t; cvta.to.shared.u64 t, %1; cvt.u32.u64 %0, t; }" : "=r"(a) : "l"(p));
    return a;
}
#define CP_ASYNC16(dst, src) \
    asm volatile("cp.async.cg.shared.global [%0], [%1], 16;" :: "r"(dst), "l"(src))
#define CP_COMMIT() asm volatile("cp.async.commit_group;" ::: "memory")
#define CP_WAIT(n)  asm volatile("cp.async.wait_group %0;" :: "n"(n) : "memory")

__device__ __forceinline__ void mma16n8k8(float c[4], const uint32_t a[4],
                                          const uint32_t b[2]) {
    asm volatile(
        "mma.sync.aligned.m16n8k8.row.col.f32.tf32.tf32.f32 "
        "{%0,%1,%2,%3}, {%4,%5,%6,%7}, {%8,%9}, {%0,%1,%2,%3};"
        : "+f"(c[0]), "+f"(c[1]), "+f"(c[2]), "+f"(c[3])
        : "r"(a[0]), "r"(a[1]), "r"(a[2]), "r"(a[3]), "r"(b[0]), "r"(b[1]));
}

// ---------------------------------------------------------------------------
// tf32 GEMM, cp.async 3-stage, 128 threads, 4 warps (2Mx2N), warp tile 64x64,
// 3 CTAs/SM. C[M,N] = alpha*A@B^T (+R). Modes: PLAIN / ROUND / SILU / ROPE.
// Optional split-K (SK=2).
// ---------------------------------------------------------------------------
#define MODE_PLAIN 0
#define MODE_ROUND 1
#define MODE_SILU  2
#define MODE_ROPE  3

#define BM 128
#define BN 128
#define BK 16
#define RS 20
#define STG_F   (2 * 128 * RS)
#define B_F     (128 * RS)
#define STAGES  3
#define GEMM_SMEM (STAGES * STG_F * 4)    // 61440

template<int MODE>
__global__ __launch_bounds__(128, 3)
void tf32_gemm(const float* __restrict__ A, int lda, long long sAz,
               const float* __restrict__ B, int ldb, long long sBz,
               float* __restrict__ C, int ldc, long long sCz,
               const float* __restrict__ R, int K, float alpha,
               int SK, long long sSkz)
{
    extern __shared__ float sm[];
    const uint32_t smb = smem_u32(sm);

    const int tid  = threadIdx.x;
    const int warp = tid >> 5, lane = tid & 31;
    const int wm = warp & 1;
    const int wn = warp >> 1;
    const int g  = lane >> 2;
    const int tg = lane & 3;

    int bzr = blockIdx.z;
    int sk = 0;
    if (SK == 2) { sk = bzr & 1; bzr >>= 1; }
    const long long bz = bzr;
    A += bz * sAz + (long long)sk * K;
    B += bz * sBz + (long long)sk * K;
    C += bz * sCz + (long long)sk * sSkz;
    const float* Rp = R ? (R + bz * sCz) : nullptr;
    const int row0 = blockIdx.y * BM;
    const int col0 = blockIdx.x * BN;

    auto fill = [&](int st, int k0) {
        uint32_t base = smb + st * (STG_F * 4);
#pragma unroll
        for (int j = 0; j < 8; j++) {
            int id = tid + 128 * j;           // 0..1023
            int isB = id >> 9;
            int r  = (id & 511) >> 2;         // 0..127
            int kc = id & 3;
            long long srow;
            if (isB) {
                int n = col0 + r;
                if (MODE == MODE_SILU) {
                    srow = (n >> 1) + (n & 1) * FFDIM;
                } else if (MODE == MODE_ROPE) {
                    if (n < 2048) {
                        int m = n & 1023;
                        srow = (n & 1024) + (m >> 1) + (m & 1) * 512;
                    } else srow = n;
                } else srow = n;
            } else srow = row0 + r;
            const float* src = (isB ? B + srow * ldb : A + srow * lda) + k0 + kc * 4;
            uint32_t dst = base + (isB ? B_F * 4 : 0) + r * (RS * 4) + kc * 16;
            CP_ASYNC16(dst, src);
        }
    };

    float acc[4][8][4];
#pragma unroll
    for (int mi = 0; mi < 4; mi++)
#pragma unroll
        for (int ni = 0; ni < 8; ni++)
#pragma unroll
            for (int j = 0; j < 4; j++) acc[mi][ni][j] = 0.0f;

    const int NK = K / BK;
    fill(0, 0);       CP_COMMIT();
    fill(1, BK);      CP_COMMIT();

    int st = 0;
    for (int it = 0; it < NK; it++) {
        CP_WAIT(1);
        __syncthreads();

        const float* sA = sm + st * STG_F;
        const float* sB = sA + B_F;
#pragma unroll
        for (int kk = 0; kk < BK; kk += 8) {
            uint32_t af[4][4], bf[8][2];
#pragma unroll
            for (int mi = 0; mi < 4; mi++) {
                int r = wm * 64 + mi * 16 + g;
                af[mi][0] = __float_as_uint(sA[r * RS + kk + tg]);
                af[mi][1] = __float_as_uint(sA[(r + 8) * RS + kk + tg]);
                af[mi][2] = __float_as_uint(sA[r * RS + kk + tg + 4]);
                af[mi][3] = __float_as_uint(sA[(r + 8) * RS + kk + tg + 4]);
            }
#pragma unroll
            for (int ni = 0; ni < 8; ni++) {
                int c = wn * 64 + ni * 8 + g;
                bf[ni][0] = __float_as_uint(sB[c * RS + kk + tg]);
                bf[ni][1] = __float_as_uint(sB[c * RS + kk + tg + 4]);
            }
#pragma unroll
            for (int mi = 0; mi < 4; mi++)
#pragma unroll
                for (int ni = 0; ni < 8; ni++)
                    mma16n8k8(acc[mi][ni], af[mi], bf[ni]);
        }

        int nf = it + 2;
        if (nf < NK) {
            int fst = st + 2; if (fst >= STAGES) fst -= STAGES;
            fill(fst, nf * BK);
        }
        CP_COMMIT();
        if (++st == STAGES) st = 0;
    }

    // ---- epilogue ----
#pragma unroll
    for (int mi = 0; mi < 4; mi++) {
        long long r = row0 + wm * 64 + mi * 16 + g;
#pragma unroll
        for (int ni = 0; ni < 8; ni++) {
            int c = col0 + wn * 64 + ni * 8 + tg * 2;

            if (MODE == MODE_SILU) {
                int oc = c >> 1;
                float x0 = acc[mi][ni][0], u0 = acc[mi][ni][1];
                float x1 = acc[mi][ni][2], u1 = acc[mi][ni][3];
                C[r * ldc + oc]       = round_tf32(x0 / (1.0f + expf(-x0)) * u0);
                C[(r + 8) * ldc + oc] = round_tf32(x1 / (1.0f + expf(-x1)) * u1);
                continue;
            }

            float2 v0, v1;
            v0.x = acc[mi][ni][0] * alpha;  v0.y = acc[mi][ni][1] * alpha;
            v1.x = acc[mi][ni][2] * alpha;  v1.y = acc[mi][ni][3] * alpha;

            if (MODE == MODE_ROPE) {
                if (c < 2048) {
                    int jj = (c & 1023) >> 1;
                    float freq = exp2f(-13.2877124f * ((float)jj / 512.0f));
                    int s0 = (int)(r & 1023), s1 = (int)((r + 8) & 1023);
                    float sn, cs;
                    sincosf((float)s0 * freq, &sn, &cs);
                    float a0 = v0.x * cs - v0.y * sn;
                    float b0 = v0.y * cs + v0.x * sn;
                    v0.x = a0; v0.y = b0;
                    sincosf((float)s1 * freq, &sn, &cs);
                    float a1 = v1.x * cs - v1.y * sn;
                    float b1 = v1.y * cs + v1.x * sn;
                    v1.x = a1; v1.y = b1;
                }
                v0.x = round_tf32(v0.x); v0.y = round_tf32(v0.y);
                v1.x = round_tf32(v1.x); v1.y = round_tf32(v1.y);
            }

            long long i0 = r * (long long)ldc + c;
            long long i1 = (r + 8) * (long long)ldc + c;
            if (Rp) {
                float2 r0 = *(const float2*)(Rp + i0);
                float2 r1 = *(const float2*)(Rp + i1);
                v0.x += r0.x; v0.y += r0.y;
                v1.x += r1.x; v1.y += r1.y;
            }
            if (MODE == MODE_ROUND) {
                v0.x = round_tf32(v0.x); v0.y = round_tf32(v0.y);
                v1.x = round_tf32(v1.x); v1.y = round_tf32(v1.y);
            }
            *(float2*)(C + i0) = v0;
            *(float2*)(C + i1) = v1;
        }
    }
}

// ---------------------------------------------------------------------------
// Split-K reduce: out = round(p0 + p1 (+ R))
// ---------------------------------------------------------------------------
__global__ void reduce_round_kernel(const float* __restrict__ part, long long skStride,
                                    const float* __restrict__ R, float* __restrict__ out)
{
    long long i = ((long long)blockIdx.x * 256 + threadIdx.x) * 4;
    float4 p0 = *(const float4*)(part + i);
    float4 p1 = *(const float4*)(part + skStride + i);
    float4 v;
    v.x = p0.x + p1.x; v.y = p0.y + p1.y;
    v.z = p0.z + p1.z; v.w = p0.w + p1.w;
    if (R) {
        float4 r4 = *(const float4*)(R + i);
        v.x += r4.x; v.y += r4.y; v.z += r4.z; v.w += r4.w;
    }
    v.x = round_tf32(v.x); v.y = round_tf32(v.y);
    v.z = round_tf32(v.z); v.w = round_tf32(v.w);
    *(float4*)(out + i) = v;
}

// ---------------------------------------------------------------------------
// Aux kernels
// ---------------------------------------------------------------------------
__global__ void round_weights_kernel(const float* __restrict__ src,
                                     float* __restrict__ dst)
{
    long long i = ((long long)blockIdx.x * 256 + threadIdx.x) * 4;
    float4 v = *(const float4*)(src + i);
    v.x = round_tf32(v.x); v.y = round_tf32(v.y);
    v.z = round_tf32(v.z); v.w = round_tf32(v.w);
    *(float4*)(dst + i) = v;
}

__global__ void embed_kernel(const int* __restrict__ ids,
                             const float* __restrict__ embed, float* __restrict__ h)
{
    int bs = blockIdx.x;
    long long tok = ids[bs];
    const float4* src = (const float4*)(embed + tok * DIM);
    float4 v = src[threadIdx.x];
    v.x = round_tf32(v.x); v.y = round_tf32(v.y);
    v.z = round_tf32(v.z); v.w = round_tf32(v.w);
    ((float4*)(h + (long long)bs * DIM))[threadIdx.x] = v;
}

__global__ void transpose_v_kernel(const float* __restrict__ qkv, float* __restrict__ vt)
{
    __shared__ float t[32][33];
    int b = blockIdx.z;
    int s0 = blockIdx.x * 32, d0 = blockIdx.y * 32;
    int s = s0 + threadIdx.y, d = d0 + threadIdx.x;
    t[threadIdx.y][threadIdx.x] = qkv[((long long)b * SEQ + s) * 3072 + 2048 + d];
    __syncthreads();
    int dd = d0 + threadIdx.y, ss = s0 + threadIdx.x;
    vt[((long long)b * DIM + dd) * SEQ + ss] = round_tf32(t[threadIdx.x][threadIdx.y]);
}

// softmax over (p0+p1)*scale rows; writes rounded probs
__global__ void softmax_split_kernel(const float* __restrict__ part, long long skStride,
                                     float* __restrict__ Sm, float scale)
{
    __shared__ float red[256];
    long long row = blockIdx.x;
    const float* r0 = part + row * SEQ;
    const float* r1 = r0 + skStride;
    int t = threadIdx.x;
    float4 a = ((const float4*)r0)[t];
    float4 b = ((const float4*)r1)[t];
    float4 v;
    v.x = (a.x + b.x) * scale; v.y = (a.y + b.y) * scale;
    v.z = (a.z + b.z) * scale; v.w = (a.w + b.w) * scale;

    float m = fmaxf(fmaxf(v.x, v.y), fmaxf(v.z, v.w));
    red[t] = m; __syncthreads();
    for (int w = 128; w > 0; w >>= 1) { if (t < w) red[t] = fmaxf(red[t], red[t + w]); __syncthreads(); }
    m = red[0]; __syncthreads();
    float e0 = expf(v.x - m), e1 = expf(v.y - m), e2 = expf(v.z - m), e3 = expf(v.w - m);
    red[t] = e0 + e1 + e2 + e3; __syncthreads();
    for (int w = 128; w > 0; w >>= 1) { if (t < w) red[t] += red[t + w]; __syncthreads(); }
    float inv = 1.0f / red[0];
    float* out = Sm + row * SEQ;
    ((float4*)out)[t] = make_float4(round_tf32(e0 * inv), round_tf32(e1 * inv),
                                    round_tf32(e2 * inv), round_tf32(e3 * inv));
}

// ---------------------------------------------------------------------------
// Host side
// ---------------------------------------------------------------------------
template<int MODE>
static void gemm(const float* A, int lda, long long sAz,
                 const float* B, int ldb, long long sBz,
                 float* C, int ldc, long long sCz,
                 const float* R, int M, int N, int K, float alpha, int bz,
                 int SK = 1, long long sSkz = 0)
{
    dim3 grid(N / BN, M / BM, bz * SK);
    tf32_gemm<MODE><<<grid, 128, GEMM_SMEM>>>(A, lda, sAz, B, ldb, sBz,
                                              C, ldc, sCz, R, K / SK, alpha,
                                              SK, sSkz);
}

extern "C" void kernel_launch(void* const* d_in, const int* in_sizes, int n_in,
                              void* d_out, int out_size)
{
    (void)in_sizes; (void)n_in; (void)out_size;
    const int*   ids    = (const int*)d_in[0];
    const float* blocks = (const float*)d_in[1];
    float*       out    = (float*)d_out;

    static int attr_done = 0;
    if (!attr_done) {
        cudaFuncSetAttribute(tf32_gemm<MODE_PLAIN>,
                             cudaFuncAttributeMaxDynamicSharedMemorySize, GEMM_SMEM);
        cudaFuncSetAttribute(tf32_gemm<MODE_ROUND>,
                             cudaFuncAttributeMaxDynamicSharedMemorySize, GEMM_SMEM);
        cudaFuncSetAttribute(tf32_gemm<MODE_SILU>,
                             cudaFuncAttributeMaxDynamicSharedMemorySize, GEMM_SMEM);
        cudaFuncSetAttribute(tf32_gemm<MODE_ROPE>,
                             cudaFuncAttributeMaxDynamicSharedMemorySize, GEMM_SMEM);
        attr_done = 1;
    }

    float *w, *h, *qkv, *vt, *s, *a, *t, *part;
    cudaGetSymbolAddress((void**)&w,    g_w);
    cudaGetSymbolAddress((void**)&h,    g_h);
    cudaGetSymbolAddress((void**)&qkv,  g_qkv);
    cudaGetSymbolAddress((void**)&vt,   g_vt);
    cudaGetSymbolAddress((void**)&s,    g_s);
    cudaGetSymbolAddress((void**)&a,    g_a);
    cudaGetSymbolAddress((void**)&t,    g_t);
    cudaGetSymbolAddress((void**)&part, g_part);

    const long long SD3 = (long long)SEQ * 3072;
    const long long SD  = (long long)SEQ * DIM;
    const long long SS  = (long long)SEQ * SEQ;
    const long long SKS = (long long)MTOK * DIM;
    const int RED_GRID  = (int)(SKS / 4 / 256);

    round_weights_kernel<<<(int)(NWEIGHT / 4 / 256), 256>>>(blocks + LAYER0_OFF, w);
    embed_kernel<<<MTOK, 256>>>(ids, blocks, h);

    for (int l = 0; l < 2; l++) {
        const float* Wqkv = w + (long long)l * LAYER_STRIDE;
        const float* Wo   = Wqkv + 3LL * DIM * DIM;
        const float* Wgu  = Wo + (long long)DIM * DIM;
        const float* Wd   = Wgu + 2LL * FFDIM * DIM;

        gemm<MODE_ROPE>(h, DIM, 0, Wqkv, DIM, 0, qkv, 3 * DIM, 0, nullptr,
                        MTOK, 3 * DIM, DIM, 1.0f, 1);
        {
            dim3 gr(SEQ / 32, DIM / 32, BATCH);
            transpose_v_kernel<<<gr, dim3(32, 32)>>>(qkv, vt);
        }
        gemm<MODE_PLAIN>(qkv, 3 * DIM, SD3, qkv + 1024, 3 * DIM, SD3,
                         part, SEQ, SS, nullptr, SEQ, SEQ, DIM, 1.0f, BATCH,
                         2, SKS);
        softmax_split_kernel<<<BATCH * SEQ, 256>>>(part, SKS, s, 1.0f / 32.0f);
        gemm<MODE_PLAIN>(s, SEQ, SS, vt, SEQ, SD, part, DIM, SD, nullptr,
                         SEQ, DIM, SEQ, 1.0f, BATCH, 2, SKS);
        reduce_round_kernel<<<RED_GRID, 256>>>(part, SKS, nullptr, a);
        gemm<MODE_PLAIN>(a, DIM, 0, Wo, DIM, 0, part, DIM, 0, nullptr,
                         MTOK, DIM, DIM, 1.0f, 1, 2, SKS);
        reduce_round_kernel<<<RED_GRID, 256>>>(part, SKS, h, h);
        gemm<MODE_SILU>(h, DIM, 0, Wgu, DIM, 0, t, FFDIM, 0, nullptr,
                        MTOK, 2 * FFDIM, DIM, 1.0f, 1);
        gemm<MODE_PLAIN>(t, FFDIM, 0, Wd, FFDIM, 0, part, DIM, 0, nullptr,
                         MTOK, DIM, FFDIM, 1.0f, 1, 2, SKS);
        reduce_round_kernel<<<RED_GRID, 256>>>(part, SKS, h, h);
    }

    gemm<MODE_PLAIN>(h, DIM, 0, w + 2 * LAYER_STRIDE, DIM, 0, out, VOC, 0, nullptr,
                     MTOK, VOC, DIM, 1.0f, 1);
}